// round 13
// baseline (speedup 1.0000x reference)
#include <cuda_runtime.h>

#define NN 8192
#define B 128                    // time buckets (monotone bucketing)
#define PB 64                    // prep blocks (subset of GRID)
#define PTT 128                  // active prep threads per prep block
#define GRID 296                 // 148 SMs * 2 CTAs -> all resident
#define K2T 512
#define ROWS_CAP 28
#define RC2 (ROWS_CAP / 2)       // 14
#define G2 (2 * GRID)            // 592

// ---- device scratch (no allocation) ----
__device__ int    g_histT[B][PB];
__device__ int    g_histA[B][PB];
__device__ float  g_regp[PB];
__device__ float4 g_ts4[NN / 4];    // times, bucket-sorted
__device__ float4 g_ps4[NN / 4];    // NEGATED preds, same order
__device__ float4 g_row4[NN];       // active rows: (t_i, 1+p_i, bits(sfx), bits(bkt))
__device__ int    g_M;
__device__ float  g_rank[GRID];
__device__ int    g_cnt[GRID];
__device__ volatile unsigned g_bar0;   // hist published (prep blocks)
__device__ volatile unsigned g_bar1;   // sort done (prep blocks)
__device__ unsigned g_ticket;          // rank completion

union Q4 { float4 f4; ulonglong2 u2; };

__device__ __forceinline__ unsigned long long addf32x2(
    unsigned long long a, unsigned long long b)
{
    unsigned long long r;
    asm("add.rn.f32x2 %0, %1, %2;" : "=l"(r) : "l"(a), "l"(b));
    return r;
}

__global__ void __launch_bounds__(K2T, 2)
svm_fused(const float* __restrict__ pred,
          const float* __restrict__ target,
          float* __restrict__ out)
{
    const int tid  = threadIdx.x;
    const int bid  = blockIdx.x;
    const int w    = tid >> 5;
    const int lane = tid & 31;
    const unsigned lt = (1u << lane) - 1u;

    // =================== PREP (blocks 0..PB-1) ===================
    __shared__ int s_wh[4][B];       // per-warp bucket counts (all)
    __shared__ int s_wha[4][B];      // per-warp bucket counts (active)
    __shared__ int s_tot[B], s_my[B], s_tota[B], s_mya[B];
    __shared__ int s_sc[B], s_sca[B];
    __shared__ float s_reg[PTT];

    if (bid < PB) {                  // bid uniform: internal syncs legal
        if (tid < 4 * B)  { ((int*)s_wh)[tid] = 0; ((int*)s_wha)[tid] = 0; }
        __syncthreads();

        float tval = 0.f, pval = 0.f;
        int   myb = 0, lr = 0, lra = 0;
        bool  act = false;
        if (tid < PTT) {             // warps 0..3 fully active
            const int i = bid * PTT + tid;
            const float2 te = ((const float2*)target)[i];
            pval = pred[i];
            tval = te.x;
            int b = (int)(tval * (B / 100.0f));
            myb = b < 0 ? 0 : (b > B - 1 ? B - 1 : b);
            act = (te.y != 0.f);
            float d = pval - tval;
            if (!act) d = fmaxf(d, 0.f);
            s_reg[tid] = d * d;

            const unsigned mm = __match_any_sync(0xffffffffu, myb);
            lr = __popc(mm & lt);
            if (lane == (__ffs(mm) - 1)) s_wh[w][myb] = __popc(mm);
            const unsigned am = __ballot_sync(0xffffffffu, act);
            const unsigned mma = mm & am;
            lra = __popc(mma & lt);
            if (act && lane == (__ffs(mma) - 1)) s_wha[w][myb] = __popc(mma);
        }
        __syncthreads();

        if (tid < B) {               // publish per-block bucket totals
            const int h  = s_wh[0][tid] + s_wh[1][tid] + s_wh[2][tid] + s_wh[3][tid];
            const int ha = s_wha[0][tid] + s_wha[1][tid] + s_wha[2][tid] + s_wha[3][tid];
            g_histT[tid][bid] = h;
            g_histA[tid][bid] = ha;
        }
        // regression partial (tree over 128)
        #pragma unroll
        for (int s = PTT / 2; s > 0; s >>= 1) {
            __syncthreads();
            if (tid < s) s_reg[tid] += s_reg[tid + s];
        }
        __syncthreads();
        if (tid == 0) g_regp[bid] = s_reg[0];

        __threadfence();
        __syncthreads();
        if (tid == 0) {
            atomicAdd((unsigned*)&g_bar0, 1u);
            while (g_bar0 < PB) { __nanosleep(64); }
        }
        __syncthreads();
        __threadfence();

        // totals + my-block offsets (row of 64 ints contiguous -> int4)
        if (tid < B) {
            int tot = 0, my = 0, tota = 0, mya = 0;
            const int4* rT = (const int4*)&g_histT[tid][0];
            const int4* rA = (const int4*)&g_histA[tid][0];
            #pragma unroll
            for (int q = 0; q < PB / 4; ++q) {
                const int4 v = rT[q], va = rA[q];
                const int blk = 4 * q;
                tot += v.x + v.y + v.z + v.w;
                tota += va.x + va.y + va.z + va.w;
                my  += (blk     < bid ? v.x : 0) + (blk + 1 < bid ? v.y : 0)
                     + (blk + 2 < bid ? v.z : 0) + (blk + 3 < bid ? v.w : 0);
                mya += (blk     < bid ? va.x : 0) + (blk + 1 < bid ? va.y : 0)
                     + (blk + 2 < bid ? va.z : 0) + (blk + 3 < bid ? va.w : 0);
            }
            s_tot[tid] = tot; s_my[tid] = my; s_tota[tid] = tota; s_mya[tid] = mya;
            s_sc[tid] = tot;  s_sca[tid] = tota;
        }
        __syncthreads();
        #pragma unroll
        for (int off = 1; off < B; off <<= 1) {   // inclusive scans
            int v = 0, va = 0;
            if (tid < B && tid >= off) { v = s_sc[tid - off]; va = s_sca[tid - off]; }
            __syncthreads();
            if (tid < B) { s_sc[tid] += v; s_sca[tid] += va; }
            __syncthreads();
        }

        // stable scatter (store NEGATED pred in the sorted array)
        if (tid < PTT) {
            const int b = myb;
            int cw = 0, cwa = 0;
            #pragma unroll
            for (int w2 = 0; w2 < 3; ++w2)
                if (w2 < w) { cw += s_wh[w2][b]; cwa += s_wha[w2][b]; }
            const int gstb = s_sc[b] - s_tot[b];
            const int pos  = gstb + s_my[b] + cw + lr;
            ((float*)g_ts4)[pos] = tval;
            ((float*)g_ps4)[pos] = -pval;
            if (act) {
                const int apos = (s_sca[b] - s_tota[b]) + s_mya[b] + cwa + lra;
                g_row4[apos] = make_float4(tval, 1.0f + pval,
                                           __int_as_float(s_sc[b]),   // sfx
                                           __int_as_float(gstb));     // bkt
            }
        }
        if (bid == 0 && tid == 0) g_M = s_sca[B - 1];
        __threadfence();
        __syncthreads();
        if (tid == 0) atomicAdd((unsigned*)&g_bar1, 1u);
    }

    // =================== grid-wide wait for sorted data ===================
    if (tid == 0) { while (g_bar1 < PB) { __nanosleep(128); } }
    __syncthreads();
    __threadfence();

    // =================== RANK (all blocks) ===================
    const int loA = 256 * w;
    const int loB = 7936 - 256 * w;
    const float4 tA0 = g_ts4[(loA >> 2) + 2 * lane], tA1 = g_ts4[(loA >> 2) + 2 * lane + 1];
    const float4 tB0 = g_ts4[(loB >> 2) + 2 * lane], tB1 = g_ts4[(loB >> 2) + 2 * lane + 1];
    Q4 pA0, pA1, pB0, pB1;
    pA0.f4 = g_ps4[(loA >> 2) + 2 * lane]; pA1.f4 = g_ps4[(loA >> 2) + 2 * lane + 1];
    pB0.f4 = g_ps4[(loB >> 2) + 2 * lane]; pB1.f4 = g_ps4[(loB >> 2) + 2 * lane + 1];

    const int M  = g_M;
    const int m0 = G2 - 1 - bid;
    const int E  = (M > bid) ? min(RC2, (M - bid + G2 - 1) / G2) : 0;
    const int O  = (M > m0)  ? min(RC2, (M - m0  + G2 - 1) / G2) : 0;
    const int nrows = E + O;

    __shared__ float4 s_row[ROWS_CAP];
    if (tid < ROWS_CAP) {
        const int k = tid >> 1;
        const bool odd = tid & 1;
        const int idx = G2 * k + (odd ? m0 : bid);
        if (idx < M) s_row[odd ? (E + k) : k] = g_row4[idx];
    }
    __syncthreads();

    float a0 = 0.f, a1 = 0.f, a2 = 0.f, a3 = 0.f;
    int cnt = 0;

// packed clean: 2 elems, 1 ADD.f32x2 + 2 FMNMX + 2 FFMA
#define CLEAN2(np2, accX, accY) { \
    Q4 d_; d_.u2.x = addf32x2(cc2, (np2)); \
    const float h0_ = fmaxf(d_.f4.x, 0.f); \
    const float h1_ = fmaxf(d_.f4.y, 0.f); \
    accX = fmaf(h0_, h0_, accX); accY = fmaf(h1_, h1_, accY); }
#define CMP1(tv, npv, kk, dd, acc) \
    { if ((tv) > ti) { const float h = fmaxf(cc + (npv), 0.f); acc = fmaf(h, h, acc); if ((kk) < (dd)) cnt++; } }

    float4 f = (nrows > 0) ? s_row[0] : make_float4(0.f, 0.f, 0.f, 0.f);
    #pragma unroll 1
    for (int r = 0; r < nrows; ++r) {
        const float4 fn = s_row[(r + 1 < nrows) ? r + 1 : r];   // prefetch
        const float ti = f.x, cc = f.y;
        const int sfx = __float_as_int(f.z);
        const int bkt = __float_as_int(f.w);
        unsigned long long cc2;
        asm("mov.b64 %0, {%1, %1};" : "=l"(cc2) : "f"(cc));
        if (tid == 0) cnt += NN - sfx;               // analytic suffix count

        if (bkt < loA + 256) {
            if (sfx <= loA) {
                CLEAN2(pA0.u2.x, a0, a1) CLEAN2(pA0.u2.y, a0, a1)
                CLEAN2(pA1.u2.x, a0, a1) CLEAN2(pA1.u2.y, a0, a1)
            } else {
                const int dd = sfx - (loA + 8 * lane);
                CMP1(tA0.x, pA0.f4.x, 0, dd, a0) CMP1(tA0.y, pA0.f4.y, 1, dd, a1)
                CMP1(tA0.z, pA0.f4.z, 2, dd, a0) CMP1(tA0.w, pA0.f4.w, 3, dd, a1)
                CMP1(tA1.x, pA1.f4.x, 4, dd, a0) CMP1(tA1.y, pA1.f4.y, 5, dd, a1)
                CMP1(tA1.z, pA1.f4.z, 6, dd, a0) CMP1(tA1.w, pA1.f4.w, 7, dd, a1)
            }
        }
        if (bkt < loB + 256) {
            if (sfx <= loB) {
                CLEAN2(pB0.u2.x, a2, a3) CLEAN2(pB0.u2.y, a2, a3)
                CLEAN2(pB1.u2.x, a2, a3) CLEAN2(pB1.u2.y, a2, a3)
            } else {
                const int dd = sfx - (loB + 8 * lane);
                CMP1(tB0.x, pB0.f4.x, 0, dd, a2) CMP1(tB0.y, pB0.f4.y, 1, dd, a3)
                CMP1(tB0.z, pB0.f4.z, 2, dd, a2) CMP1(tB0.w, pB0.f4.w, 3, dd, a3)
                CMP1(tB1.x, pB1.f4.x, 4, dd, a2) CMP1(tB1.y, pB1.f4.y, 5, dd, a3)
                CMP1(tB1.z, pB1.f4.z, 6, dd, a2) CMP1(tB1.w, pB1.f4.w, 7, dd, a3)
            }
        }
        f = fn;
    }
    const float rank_acc = (a0 + a1) + (a2 + a3);

    // block reduction (deterministic tree)
    __shared__ float red_r[K2T];
    __shared__ int   red_c[K2T];
    red_r[tid] = rank_acc;
    red_c[tid] = cnt;
    __syncthreads();
    #pragma unroll
    for (int s = K2T / 2; s > 0; s >>= 1) {
        if (tid < s) { red_r[tid] += red_r[tid + s]; red_c[tid] += red_c[tid + s]; }
        __syncthreads();
    }

    __shared__ bool s_last;
    if (tid == 0) {
        g_rank[bid] = red_r[0];
        g_cnt[bid]  = red_c[0];
        __threadfence();
        const unsigned old = atomicAdd(&g_ticket, 1u);
        s_last = (old == GRID - 1);
    }
    __syncthreads();

    if (s_last) {
        __threadfence();
        __shared__ double sr[K2T], sc[K2T], sg[K2T];
        double rank = 0.0, c = 0.0, reg = 0.0;
        if (tid < GRID) { rank = (double)g_rank[tid]; c = (double)g_cnt[tid]; }
        if (tid < PB)   { reg  = (double)g_regp[tid]; }
        sr[tid] = rank; sc[tid] = c; sg[tid] = reg;
        __syncthreads();
        #pragma unroll
        for (int s = K2T / 2; s > 0; s >>= 1) {
            if (tid < s) { sr[tid] += sr[tid + s]; sc[tid] += sc[tid + s]; sg[tid] += sg[tid + s]; }
            __syncthreads();
        }
        if (tid == 0) {
            double cc = sc[0];
            if (cc < 1.0) cc = 1.0;
            const double R = 0.5;
            out[0] = (float)(R * (sr[0] / cc) + (1.0 - R) * (sg[0] / (double)NN));
            g_ticket = 0;            // reset for next graph replay
            g_bar0 = 0;
            g_bar1 = 0;
        }
    }
}

extern "C" void kernel_launch(void* const* d_in, const int* in_sizes, int n_in,
                              void* d_out, int out_size)
{
    // Robust input mapping: pred has NN elements, target has 2*NN.
    int pred_idx = 0, tgt_idx = 1;
    if (n_in >= 2 && in_sizes[0] > in_sizes[1]) { pred_idx = 1; tgt_idx = 0; }
    const float* pred   = (const float*)d_in[pred_idx];
    const float* target = (const float*)d_in[tgt_idx];
    float* out = (float*)d_out;

    svm_fused<<<GRID, K2T>>>(pred, target, out);
}